// round 12
// baseline (speedup 1.0000x reference)
#include <cuda_runtime.h>
#include <cuda_fp16.h>
#include <cstdint>
#include <cstddef>

// Problem constants (match reference)
#define NMAX 100000
#define EMAX 1600000
#define K_DIM 128

// ---- Scratch (device globals; no allocations allowed) ----
__device__ int    g_deg[NMAX];
__device__ int    g_rowptr[NMAX + 1];
__device__ int    g_fill[NMAX];
__device__ int    g_col[EMAX];
__device__ int    g_chainval[128];
__device__ int    g_flag[128];
__device__ __half g_x16[(size_t)NMAX * 128];  // fp16 copy of input x
__device__ __half g_agg[(size_t)NMAX * 128];  // mean-aggregated features (fp16)
__device__ __half g_ha[(size_t)NMAX * 128];   // layer-0 output (fp16)
__device__ __half g_hb[(size_t)NMAX * 128];   // layer-1 output (fp16)
__device__ __half g_xl[(size_t)NMAX * 64];    // layer-2 aggregated-path (fp16)
__device__ float  g_xr[(size_t)NMAX * 64];    // layer-2 self-path (fp32)

// ============================================================
// Packed prep kernel: blocks [0, CVT_B) convert x->fp16 (grid-stride),
// blocks [CVT_B, CVT_B+HIST_B) histogram dst (grid-stride).
// memsetAsync(g_deg, g_flag) precedes this launch on the stream.
// ============================================================
#define CVT_B  296
#define HIST_B 148

__global__ __launch_bounds__(256) void prep_k(
    const float4* __restrict__ x, uint2* __restrict__ o, int n4,
    const int* __restrict__ dst, int e)
{
    if (blockIdx.x < CVT_B) {
        for (int i = blockIdx.x * 256 + threadIdx.x; i < n4; i += CVT_B * 256) {
            float4 v = x[i];
            __half2 h0 = __floats2half2_rn(v.x, v.y);
            __half2 h1 = __floats2half2_rn(v.z, v.w);
            uint2 u;
            u.x = *(uint32_t*)&h0;
            u.y = *(uint32_t*)&h1;
            o[i] = u;
        }
    } else {
        int e4 = e >> 2;
        int bid = blockIdx.x - CVT_B;
        for (int i = bid * 256 + threadIdx.x; i < e4; i += HIST_B * 256) {
            int4 d = *(const int4*)(dst + i * 4);
            atomicAdd(&g_deg[d.x], 1);
            atomicAdd(&g_deg[d.y], 1);
            atomicAdd(&g_deg[d.z], 1);
            atomicAdd(&g_deg[d.w], 1);
        }
        // tail
        if (bid == 0 && threadIdx.x < (e & 3))
            atomicAdd(&g_deg[dst[e4 * 4 + threadIdx.x]], 1);
    }
}

// ============================================================
// Single-pass chained scan (decoupled lookback over <=128 blocks):
// computes rowptr/fill = exclusive scan of deg. Deterministic.
// ============================================================
__global__ __launch_bounds__(1024) void scan_k(int n, int nb) {
    __shared__ int sh[1024];
    __shared__ int sh_prefix;
    int tid = threadIdx.x;
    int bid = blockIdx.x;
    int i = bid * 1024 + tid;
    int v = (i < n) ? g_deg[i] : 0;
    sh[tid] = v;
    __syncthreads();
#pragma unroll
    for (int off = 1; off < 1024; off <<= 1) {
        int t = (tid >= off) ? sh[tid - off] : 0;
        __syncthreads();
        sh[tid] += t;
        __syncthreads();
    }
    int total = sh[1023];

    if (tid == 0) {
        int prefix = 0;
        if (bid > 0) {
            while (atomicAdd(&g_flag[bid - 1], 0) == 0) { }
            prefix = g_chainval[bid - 1];
        }
        g_chainval[bid] = prefix + total;
        __threadfence();
        atomicExch(&g_flag[bid], 1);
        sh_prefix = prefix;
        if (bid == nb - 1) g_rowptr[n] = prefix + total;
    }
    __syncthreads();

    if (i < n) {
        int r = sh[tid] - v + sh_prefix;   // exclusive
        g_rowptr[i] = r;
        g_fill[i]   = r;
    }
}

__global__ void scatter_k(const int* __restrict__ src, const int* __restrict__ dst, int e) {
    int i4 = blockIdx.x * blockDim.x + threadIdx.x;
    int base = i4 * 4;
    if (base + 3 < e) {
        int4 d = *(const int4*)(dst + base);
        int4 s = *(const int4*)(src + base);
        int p0 = atomicAdd(&g_fill[d.x], 1);
        int p1 = atomicAdd(&g_fill[d.y], 1);
        int p2 = atomicAdd(&g_fill[d.z], 1);
        int p3 = atomicAdd(&g_fill[d.w], 1);
        g_col[p0] = s.x; g_col[p1] = s.y; g_col[p2] = s.z; g_col[p3] = s.w;
    } else {
        for (int j = base; j < e; j++) {
            int p = atomicAdd(&g_fill[dst[j]], 1);
            g_col[p] = src[j];
        }
    }
}

// ============================================================
// mma / ldmatrix / cp.async helpers
// ============================================================
__device__ __forceinline__ uint32_t smem_u32(const void* p) {
    return (uint32_t)__cvta_generic_to_shared(p);
}

__device__ __forceinline__ void ldsm_x4(uint32_t& r0, uint32_t& r1, uint32_t& r2, uint32_t& r3,
                                        uint32_t a) {
    asm volatile("ldmatrix.sync.aligned.m8n8.x4.shared.b16 {%0,%1,%2,%3}, [%4];"
                 : "=r"(r0), "=r"(r1), "=r"(r2), "=r"(r3) : "r"(a));
}
__device__ __forceinline__ void ldsm_x2(uint32_t& r0, uint32_t& r1, uint32_t a) {
    asm volatile("ldmatrix.sync.aligned.m8n8.x2.shared.b16 {%0,%1}, [%2];"
                 : "=r"(r0), "=r"(r1) : "r"(a));
}
__device__ __forceinline__ void mma_f16(
    float c[4], uint32_t a0, uint32_t a1, uint32_t a2, uint32_t a3,
    uint32_t b0, uint32_t b1)
{
    asm volatile(
        "mma.sync.aligned.m16n8k16.row.col.f32.f16.f16.f32 "
        "{%0,%1,%2,%3}, {%4,%5,%6,%7}, {%8,%9}, {%0,%1,%2,%3};"
        : "+f"(c[0]), "+f"(c[1]), "+f"(c[2]), "+f"(c[3])
        : "r"(a0), "r"(a1), "r"(a2), "r"(a3), "r"(b0), "r"(b1));
}

__device__ __forceinline__ void cp_async16(uint32_t dst, const void* src, int srcbytes) {
    asm volatile("cp.async.cg.shared.global [%0], [%1], 16, %2;"
                 :: "r"(dst), "l"(src), "r"(srcbytes));
}
__device__ __forceinline__ void cp_commit() {
    asm volatile("cp.async.commit_group;" ::: "memory");
}
template <int N>
__device__ __forceinline__ void cp_wait() {
    asm volatile("cp.async.wait_group %0;" :: "n"(N) : "memory");
}

// ============================================================
// Fused layer GEMM (layers 0/1, agg-first):
//   H = relu( Agg @ Wl + X @ Wr + bias )   (fp16 out)
// BM=128; 512 threads; warp tile M=32 x N=32.
// ============================================================
__global__ __launch_bounds__(512) void gemm_l01(
    const __half* __restrict__ Agg, const __half* __restrict__ X,
    const float* __restrict__ Wl, const float* __restrict__ Wr,
    const float* __restrict__ bias,
    __half* __restrict__ H, int n)
{
    constexpr int DOUT = 128;
    constexpr int BM = 128;
    constexpr int KP = K_DIM + 8;        // 136 halves = 272 B row stride
    constexpr int NF = 4;                // 8-col strips per warp

    extern __shared__ __half smh[];
    __half (*Wt)[DOUT][KP]   = (__half(*)[DOUT][KP])smh;                    // [2][128][KP]
    __half (*As)[2][BM][KP]  = (__half(*)[2][BM][KP])(smh + 2 * DOUT * KP); // [2][2][128][KP]

    const int tid = threadIdx.x;
    const int nTiles = (n + BM - 1) / BM;

    int tile0 = blockIdx.x;
    for (int v = 0; v < 8; v++) {
        int idx = tid + v * 512;
        int which = idx >> 11;
        int rem = idx & 2047;
        int rr  = rem >> 4;
        int ch  = rem & 15;
        int gr  = tile0 * BM + rr;
        bool ok = (tile0 < nTiles) && (gr < n);
        const __half* base = which ? X : Agg;
        const __half* src = ok ? (base + (size_t)gr * K_DIM + ch * 8) : base;
        cp_async16(smem_u32(&As[0][which][rr][ch * 8]), src, ok ? 16 : 0);
    }
    cp_commit();

    for (int w = 0; w < 2; w++) {
        const float* W = w ? Wr : Wl;
#pragma unroll
        for (int v = 0; v < (K_DIM * DOUT / 4) / 512; v++) {
            int idx = tid + v * 512;
            int kk  = idx / (DOUT / 4);
            int n4  = (idx % (DOUT / 4)) * 4;
            float4 bv = *(const float4*)(W + (size_t)kk * DOUT + n4);
            Wt[w][n4 + 0][kk] = __float2half_rn(bv.x);
            Wt[w][n4 + 1][kk] = __float2half_rn(bv.y);
            Wt[w][n4 + 2][kk] = __float2half_rn(bv.z);
            Wt[w][n4 + 3][kk] = __float2half_rn(bv.w);
        }
    }

    const int warp = tid >> 5;
    const int lane = tid & 31;
    const int g    = lane >> 2;
    const int tig  = lane & 3;
    const int rgrp = warp & 3;
    const int nq   = warp >> 2;
    const int wrow = rgrp * 32;
    const int col0 = nq * 32;

    const int a_row0 = wrow + (lane & 15);
    const int a_row1 = wrow + 16 + (lane & 15);
    const int a_koff = (lane >> 4) << 3;
    const int b_row  = (lane & 7);
    const int b_koff = ((lane >> 3) & 1) << 3;

    int buf = 0;
    for (int tile = tile0; tile < nTiles; tile += gridDim.x) {
        int nextTile = tile + gridDim.x;
        if (nextTile < nTiles) {
            for (int v = 0; v < 8; v++) {
                int idx = tid + v * 512;
                int which = idx >> 11;
                int rem = idx & 2047;
                int rr  = rem >> 4;
                int ch  = rem & 15;
                int gr  = nextTile * BM + rr;
                bool ok = (gr < n);
                const __half* base = which ? X : Agg;
                const __half* src = ok ? (base + (size_t)gr * K_DIM + ch * 8) : base;
                cp_async16(smem_u32(&As[buf ^ 1][which][rr][ch * 8]), src, ok ? 16 : 0);
            }
            cp_commit();
            cp_wait<1>();
        } else {
            cp_wait<0>();
        }
        __syncthreads();

        const int row0 = tile * BM;

        float acc[2][NF][4];
#pragma unroll
        for (int at = 0; at < 2; at++)
#pragma unroll
            for (int f = 0; f < NF; f++)
#pragma unroll
                for (int j = 0; j < 4; j++) acc[at][f][j] = 0.f;

#pragma unroll
        for (int kstep = 0; kstep < K_DIM / 16; kstep++) {
            const int kb = kstep * 16;
            {
                uint32_t a0, a1, a2, a3, c0, c1, c2, c3;
                ldsm_x4(a0, a1, a2, a3, smem_u32(&As[buf][0][a_row0][kb + a_koff]));
                ldsm_x4(c0, c1, c2, c3, smem_u32(&As[buf][0][a_row1][kb + a_koff]));
#pragma unroll
                for (int f = 0; f < NF; f++) {
                    uint32_t b0, b1;
                    ldsm_x2(b0, b1, smem_u32(&Wt[0][col0 + f * 8 + b_row][kb + b_koff]));
                    mma_f16(acc[0][f], a0, a1, a2, a3, b0, b1);
                    mma_f16(acc[1][f], c0, c1, c2, c3, b0, b1);
                }
            }
            {
                uint32_t a0, a1, a2, a3, c0, c1, c2, c3;
                ldsm_x4(a0, a1, a2, a3, smem_u32(&As[buf][1][a_row0][kb + a_koff]));
                ldsm_x4(c0, c1, c2, c3, smem_u32(&As[buf][1][a_row1][kb + a_koff]));
#pragma unroll
                for (int f = 0; f < NF; f++) {
                    uint32_t b0, b1;
                    ldsm_x2(b0, b1, smem_u32(&Wt[1][col0 + f * 8 + b_row][kb + b_koff]));
                    mma_f16(acc[0][f], a0, a1, a2, a3, b0, b1);
                    mma_f16(acc[1][f], c0, c1, c2, c3, b0, b1);
                }
            }
        }

#pragma unroll
        for (int at = 0; at < 2; at++) {
            const int r_lo = row0 + wrow + at * 16 + g;
            const int r_hi = r_lo + 8;
#pragma unroll
            for (int f = 0; f < NF; f++) {
                int col = col0 + f * 8 + 2 * tig;
                float bv0 = bias[col];
                float bv1 = bias[col + 1];
                if (r_lo < n) {
                    float o0 = fmaxf(acc[at][f][0] + bv0, 0.f);
                    float o1 = fmaxf(acc[at][f][1] + bv1, 0.f);
                    __half2 h = __floats2half2_rn(o0, o1);
                    *(__half2*)(H + (size_t)r_lo * DOUT + col) = h;
                }
                if (r_hi < n) {
                    float o0 = fmaxf(acc[at][f][2] + bv0, 0.f);
                    float o1 = fmaxf(acc[at][f][3] + bv1, 0.f);
                    __half2 h = __floats2half2_rn(o0, o1);
                    *(__half2*)(H + (size_t)r_hi * DOUT + col) = h;
                }
            }
        }

        __syncthreads();
        buf ^= 1;
    }
}

// ============================================================
// Layer-2 dual GEMM: xl = A @ Wl2 (fp16), xr = A @ Wr2 + b2 (fp32)
// ============================================================
__global__ __launch_bounds__(512) void gemm_h64(
    const __half* __restrict__ A,
    const float* __restrict__ Wl, const float* __restrict__ Wr,
    const float* __restrict__ bias,
    __half* __restrict__ Cl, float* __restrict__ Cr, int n)
{
    constexpr int DOUT = 64;
    constexpr int BM = 128;
    constexpr int KP = K_DIM + 8;
    constexpr int NF = 2;

    extern __shared__ __half smh[];
    __half (*Wt)[DOUT][KP] = (__half(*)[DOUT][KP])smh;
    __half (*As)[BM][KP]   = (__half(*)[BM][KP])(smh + 2 * DOUT * KP);

    const int tid = threadIdx.x;
    const int nTiles = (n + BM - 1) / BM;

    int tile0 = blockIdx.x;
    for (int v = 0; v < 4; v++) {
        int idx = tid + v * 512;
        int rr  = idx >> 4;
        int ch  = idx & 15;
        int gr  = tile0 * BM + rr;
        bool ok = (tile0 < nTiles) && (gr < n);
        const __half* src = ok ? (A + (size_t)gr * K_DIM + ch * 8) : A;
        cp_async16(smem_u32(&As[0][rr][ch * 8]), src, ok ? 16 : 0);
    }
    cp_commit();

    for (int w = 0; w < 2; w++) {
        const float* W = w ? Wr : Wl;
#pragma unroll
        for (int v = 0; v < (K_DIM * DOUT / 4) / 512; v++) {
            int idx = tid + v * 512;
            int kk  = idx / (DOUT / 4);
            int n4  = (idx % (DOUT / 4)) * 4;
            float4 bv = *(const float4*)(W + (size_t)kk * DOUT + n4);
            Wt[w][n4 + 0][kk] = __float2half_rn(bv.x);
            Wt[w][n4 + 1][kk] = __float2half_rn(bv.y);
            Wt[w][n4 + 2][kk] = __float2half_rn(bv.z);
            Wt[w][n4 + 3][kk] = __float2half_rn(bv.w);
        }
    }

    const int warp = tid >> 5;
    const int lane = tid & 31;
    const int g    = lane >> 2;
    const int tig  = lane & 3;
    const int rgrp = warp & 3;
    const int nq   = warp >> 2;
    const int wrow = rgrp * 32;
    const int col0 = nq * 16;

    const int a_row0 = wrow + (lane & 15);
    const int a_row1 = wrow + 16 + (lane & 15);
    const int a_koff = (lane >> 4) << 3;
    const int b_row  = (lane & 7);
    const int b_koff = ((lane >> 3) & 1) << 3;

    int buf = 0;
    for (int tile = tile0; tile < nTiles; tile += gridDim.x) {
        int nextTile = tile + gridDim.x;
        if (nextTile < nTiles) {
            for (int v = 0; v < 4; v++) {
                int idx = tid + v * 512;
                int rr  = idx >> 4;
                int ch  = idx & 15;
                int gr  = nextTile * BM + rr;
                bool ok = (gr < n);
                const __half* src = ok ? (A + (size_t)gr * K_DIM + ch * 8) : A;
                cp_async16(smem_u32(&As[buf ^ 1][rr][ch * 8]), src, ok ? 16 : 0);
            }
            cp_commit();
            cp_wait<1>();
        } else {
            cp_wait<0>();
        }
        __syncthreads();

        const int row0 = tile * BM;

        float acc[2][2][NF][4];
#pragma unroll
        for (int w = 0; w < 2; w++)
#pragma unroll
            for (int at = 0; at < 2; at++)
#pragma unroll
                for (int f = 0; f < NF; f++)
#pragma unroll
                    for (int j = 0; j < 4; j++) acc[w][at][f][j] = 0.f;

#pragma unroll
        for (int kstep = 0; kstep < K_DIM / 16; kstep++) {
            const int kb = kstep * 16;
            uint32_t a0, a1, a2, a3, c0, c1, c2, c3;
            ldsm_x4(a0, a1, a2, a3, smem_u32(&As[buf][a_row0][kb + a_koff]));
            ldsm_x4(c0, c1, c2, c3, smem_u32(&As[buf][a_row1][kb + a_koff]));
#pragma unroll
            for (int wsel = 0; wsel < 2; wsel++) {
#pragma unroll
                for (int f = 0; f < NF; f++) {
                    uint32_t b0, b1;
                    ldsm_x2(b0, b1, smem_u32(&Wt[wsel][col0 + f * 8 + b_row][kb + b_koff]));
                    mma_f16(acc[wsel][0][f], a0, a1, a2, a3, b0, b1);
                    mma_f16(acc[wsel][1][f], c0, c1, c2, c3, b0, b1);
                }
            }
        }

#pragma unroll
        for (int at = 0; at < 2; at++) {
            const int r_lo = row0 + wrow + at * 16 + g;
            const int r_hi = r_lo + 8;
#pragma unroll
            for (int f = 0; f < NF; f++) {
                int col = col0 + f * 8 + 2 * tig;
                if (r_lo < n) {
                    __half2 h = __floats2half2_rn(acc[0][at][f][0], acc[0][at][f][1]);
                    *(__half2*)(Cl + (size_t)r_lo * DOUT + col) = h;
                }
                if (r_hi < n) {
                    __half2 h = __floats2half2_rn(acc[0][at][f][2], acc[0][at][f][3]);
                    *(__half2*)(Cl + (size_t)r_hi * DOUT + col) = h;
                }
                float bv0 = bias[col];
                float bv1 = bias[col + 1];
                if (r_lo < n)
                    *(float2*)(Cr + (size_t)r_lo * DOUT + col) =
                        make_float2(acc[1][at][f][0] + bv0, acc[1][at][f][1] + bv1);
                if (r_hi < n)
                    *(float2*)(Cr + (size_t)r_hi * DOUT + col) =
                        make_float2(acc[1][at][f][2] + bv0, acc[1][at][f][3] + bv1);
            }
        }

        __syncthreads();
        buf ^= 1;
    }
}

// ============================================================
// Pure mean-aggregation (128-dim, fp16 -> fp16)
// ============================================================
__global__ __launch_bounds__(256) void agg_mean128(
    const __half* __restrict__ xin, __half* __restrict__ out, int n)
{
    int gw   = (blockIdx.x * blockDim.x + threadIdx.x) >> 5;
    int lane = threadIdx.x & 31;
    if (gw >= n) return;

    int beg = g_rowptr[gw];
    int end = g_rowptr[gw + 1];
    float inv = 1.f / fmaxf((float)(end - beg), 1.f);

    const uint2* X = (const uint2*)xin;
    float ax = 0.f, ay = 0.f, az = 0.f, aw = 0.f;
    float bx = 0.f, by = 0.f, bz = 0.f, bw = 0.f;

    int e = beg;
    for (; e + 8 <= end; e += 8) {
        int s0 = g_col[e + 0], s1 = g_col[e + 1], s2 = g_col[e + 2], s3 = g_col[e + 3];
        int s4 = g_col[e + 4], s5 = g_col[e + 5], s6 = g_col[e + 6], s7 = g_col[e + 7];
        uint2 v0 = X[(size_t)s0 * 32 + lane];
        uint2 v1 = X[(size_t)s1 * 32 + lane];
        uint2 v2 = X[(size_t)s2 * 32 + lane];
        uint2 v3 = X[(size_t)s3 * 32 + lane];
        uint2 v4 = X[(size_t)s4 * 32 + lane];
        uint2 v5 = X[(size_t)s5 * 32 + lane];
        uint2 v6 = X[(size_t)s6 * 32 + lane];
        uint2 v7 = X[(size_t)s7 * 32 + lane];
        float2 f;
        f = __half22float2(*(__half2*)&v0.x); ax += f.x; ay += f.y;
        f = __half22float2(*(__half2*)&v0.y); az += f.x; aw += f.y;
        f = __half22float2(*(__half2*)&v1.x); bx += f.x; by += f.y;
        f = __half22float2(*(__half2*)&v1.y); bz += f.x; bw += f.y;
        f = __half22float2(*(__half2*)&v2.x); ax += f.x; ay += f.y;
        f = __half22float2(*(__half2*)&v2.y); az += f.x; aw += f.y;
        f = __half22float2(*(__half2*)&v3.x); bx += f.x; by += f.y;
        f = __half22float2(*(__half2*)&v3.y); bz += f.x; bw += f.y;
        f = __half22float2(*(__half2*)&v4.x); ax += f.x; ay += f.y;
        f = __half22float2(*(__half2*)&v4.y); az += f.x; aw += f.y;
        f = __half22float2(*(__half2*)&v5.x); bx += f.x; by += f.y;
        f = __half22float2(*(__half2*)&v5.y); bz += f.x; bw += f.y;
        f = __half22float2(*(__half2*)&v6.x); ax += f.x; ay += f.y;
        f = __half22float2(*(__half2*)&v6.y); az += f.x; aw += f.y;
        f = __half22float2(*(__half2*)&v7.x); bx += f.x; by += f.y;
        f = __half22float2(*(__half2*)&v7.y); bz += f.x; bw += f.y;
    }
    for (; e < end; e++) {
        int s = g_col[e];
        uint2 v = X[(size_t)s * 32 + lane];
        float2 f;
        f = __half22float2(*(__half2*)&v.x); ax += f.x; ay += f.y;
        f = __half22float2(*(__half2*)&v.y); az += f.x; aw += f.y;
    }

    float ox = (ax + bx) * inv;
    float oy = (ay + by) * inv;
    float oz = (az + bz) * inv;
    float ow = (aw + bw) * inv;
    __half2 h0 = __floats2half2_rn(ox, oy);
    __half2 h1 = __floats2half2_rn(oz, ow);
    uint2 u;
    u.x = *(uint32_t*)&h0;
    u.y = *(uint32_t*)&h1;
    ((uint2*)out)[(size_t)gw * 32 + lane] = u;
}

// ============================================================
// Layer-2 aggregation + epilogue (64-dim): out = mean(xl[s]) + xr (fp32)
// ============================================================
__global__ __launch_bounds__(256) void agg_ep64h(
    const __half* __restrict__ xl, const float* __restrict__ xr,
    float* __restrict__ out, int n)
{
    int gw   = (blockIdx.x * blockDim.x + threadIdx.x) >> 5;
    int lane = threadIdx.x & 31;
    if (gw >= n) return;

    int beg = g_rowptr[gw];
    int end = g_rowptr[gw + 1];
    float inv = 1.f / fmaxf((float)(end - beg), 1.f);

    const uint32_t* X = (const uint32_t*)xl;
    float ax = 0.f, ay = 0.f, bx = 0.f, by = 0.f;

    int e = beg;
    for (; e + 8 <= end; e += 8) {
        int s0 = g_col[e + 0], s1 = g_col[e + 1], s2 = g_col[e + 2], s3 = g_col[e + 3];
        int s4 = g_col[e + 4], s5 = g_col[e + 5], s6 = g_col[e + 6], s7 = g_col[e + 7];
        uint32_t v0 = X[(size_t)s0 * 32 + lane];
        uint32_t v1 = X[(size_t)s1 * 32 + lane];
        uint32_t v2 = X[(size_t)s2 * 32 + lane];
        uint32_t v3 = X[(size_t)s3 * 32 + lane];
        uint32_t v4 = X[(size_t)s4 * 32 + lane];
        uint32_t v5 = X[(size_t)s5 * 32 + lane];
        uint32_t v6 = X[(size_t)s6 * 32 + lane];
        uint32_t v7 = X[(size_t)s7 * 32 + lane];
        float2 f;
        f = __half22float2(*(__half2*)&v0); ax += f.x; ay += f.y;
        f = __half22float2(*(__half2*)&v1); bx += f.x; by += f.y;
        f = __half22float2(*(__half2*)&v2); ax += f.x; ay += f.y;
        f = __half22float2(*(__half2*)&v3); bx += f.x; by += f.y;
        f = __half22float2(*(__half2*)&v4); ax += f.x; ay += f.y;
        f = __half22float2(*(__half2*)&v5); bx += f.x; by += f.y;
        f = __half22float2(*(__half2*)&v6); ax += f.x; ay += f.y;
        f = __half22float2(*(__half2*)&v7); bx += f.x; by += f.y;
    }
    for (; e < end; e++) {
        int s = g_col[e];
        uint32_t v = X[(size_t)s * 32 + lane];
        float2 f = __half22float2(*(__half2*)&v);
        ax += f.x; ay += f.y;
    }

    float2 r = ((const float2*)xr)[(size_t)gw * 32 + lane];
    float2 o;
    o.x = (ax + bx) * inv + r.x;
    o.y = (ay + by) * inv + r.y;
    ((float2*)out)[(size_t)gw * 32 + lane] = o;
}

// ============================================================
// Launch — single stream.
// ============================================================
extern "C" void kernel_launch(void* const* d_in, const int* in_sizes, int n_in,
                              void* d_out, int out_size)
{
    const float* x   = (const float*)d_in[0];
    const int*   ei  = (const int*)d_in[1];
    const float* Wl0 = (const float*)d_in[2];
    const float* Wr0 = (const float*)d_in[3];
    const float* b0  = (const float*)d_in[4];
    const float* Wl1 = (const float*)d_in[5];
    const float* Wr1 = (const float*)d_in[6];
    const float* b1  = (const float*)d_in[7];
    const float* Wl2 = (const float*)d_in[8];
    const float* Wr2 = (const float*)d_in[9];
    const float* b2  = (const float*)d_in[10];

    const int n = in_sizes[0] / 128;
    const int e = in_sizes[1] / 2;
    const int* src = ei;
    const int* dst = ei + e;

    void *px16, *pagg, *pha, *phb, *pxl, *pxr, *pdeg, *pflag;
    cudaGetSymbolAddress(&px16, g_x16);
    cudaGetSymbolAddress(&pagg, g_agg);
    cudaGetSymbolAddress(&pha, g_ha);
    cudaGetSymbolAddress(&phb, g_hb);
    cudaGetSymbolAddress(&pxl, g_xl);
    cudaGetSymbolAddress(&pxr, g_xr);
    cudaGetSymbolAddress(&pdeg, g_deg);
    cudaGetSymbolAddress(&pflag, g_flag);
    __half* f_x16 = (__half*)px16;
    __half* f_agg = (__half*)pagg;
    __half* f_ha  = (__half*)pha;
    __half* f_hb  = (__half*)phb;
    __half* f_xl  = (__half*)pxl;
    float*  f_xr  = (float*)pxr;

    // smem (bytes)
    constexpr int KP = K_DIM + 8;
    constexpr int SM_L01 = (2 * 128 * KP + 2 * 2 * 128 * KP) * 2;  // 208896
    constexpr int SM_H64 = (2 * 64 * KP + 2 * 128 * KP) * 2;       // 104448
    static bool attr_set = false;
    if (!attr_set) {
        cudaFuncSetAttribute(gemm_l01, cudaFuncAttributeMaxDynamicSharedMemorySize, SM_L01);
        cudaFuncSetAttribute(gemm_h64, cudaFuncAttributeMaxDynamicSharedMemorySize, SM_H64);
        attr_set = true;
    }

    const int NSM = 148;
    const int agg_blocks = (n + 7) / 8;
    const int nb = (n + 1023) / 1024;

    // Zero deg + chain flags, then packed prep (cvt || hist)
    cudaMemsetAsync(pdeg, 0, (size_t)n * sizeof(int));
    cudaMemsetAsync(pflag, 0, 128 * sizeof(int));
    prep_k<<<CVT_B + HIST_B, 256>>>((const float4*)x, (uint2*)f_x16, n * 32, dst, e);

    // Single-pass chained scan -> rowptr/fill, then scatter
    scan_k<<<nb, 1024>>>(n, nb);
    scatter_k<<<((e + 3) / 4 + 255) / 256, 256>>>(src, dst, e);

    // Layer 0: aggx = mean(x16); h1 = relu(aggx@Wl0 + x16@Wr0 + b0)
    agg_mean128<<<agg_blocks, 256>>>(f_x16, f_agg, n);
    gemm_l01<<<NSM, 512, SM_L01>>>(f_agg, f_x16, Wl0, Wr0, b0, f_ha, n);

    // Layer 1
    agg_mean128<<<agg_blocks, 256>>>(f_ha, f_agg, n);
    gemm_l01<<<NSM, 512, SM_L01>>>(f_agg, f_ha, Wl1, Wr1, b1, f_hb, n);

    // Layer 2 (transform-first, DOUT=64): xl = h2@Wl2, xr = h2@Wr2 + b2
    gemm_h64<<<NSM, 512, SM_H64>>>(f_hb, Wl2, Wr2, b2, f_xl, f_xr, n);
    agg_ep64h<<<agg_blocks, 256>>>(f_xl, f_xr, (float*)d_out, n);
}

// round 13
// speedup vs baseline: 1.3993x; 1.3993x over previous
#include <cuda_runtime.h>
#include <cuda_fp16.h>
#include <cstdint>
#include <cstddef>

// Problem constants (match reference)
#define NMAX 100000
#define EMAX 1600000
#define K_DIM 128

// ---- Scratch (device globals; no allocations allowed) ----
__device__ int    g_deg[NMAX];
__device__ int    g_rowptr[NMAX + 1];
__device__ int    g_fill[NMAX];
__device__ int    g_col[EMAX];
__device__ int    g_scan[NMAX];
__device__ int    g_bsum[128];
__device__ __half g_x16[(size_t)NMAX * 128];  // fp16 copy of input x
__device__ __half g_agg[(size_t)NMAX * 128];  // mean-aggregated features (fp16)
__device__ __half g_ha[(size_t)NMAX * 128];   // layer-0 output (fp16)
__device__ __half g_hb[(size_t)NMAX * 128];   // layer-1 output (fp16)
__device__ __half g_xl[(size_t)NMAX * 64];    // layer-2 aggregated-path (fp16)
__device__ float  g_xr[(size_t)NMAX * 64];    // layer-2 self-path (fp32)

// ============================================================
// CSR build (counting sort by dst), rebuilt every launch
// ============================================================
__global__ void hist_k(const int* __restrict__ dst, int e) {
    int i4 = blockIdx.x * blockDim.x + threadIdx.x;
    int base = i4 * 4;
    if (base + 3 < e) {
        int4 d = *(const int4*)(dst + base);
        atomicAdd(&g_deg[d.x], 1);
        atomicAdd(&g_deg[d.y], 1);
        atomicAdd(&g_deg[d.z], 1);
        atomicAdd(&g_deg[d.w], 1);
    } else {
        for (int j = base; j < e; j++) atomicAdd(&g_deg[dst[j]], 1);
    }
}

// Phase A: per-block inclusive scan of 1024 deg entries
__global__ __launch_bounds__(1024) void scanA_k(int n) {
    __shared__ int sh[1024];
    int tid = threadIdx.x;
    int i = blockIdx.x * 1024 + tid;
    int v = (i < n) ? g_deg[i] : 0;
    sh[tid] = v;
    __syncthreads();
#pragma unroll
    for (int off = 1; off < 1024; off <<= 1) {
        int t = (tid >= off) ? sh[tid - off] : 0;
        __syncthreads();
        sh[tid] += t;
        __syncthreads();
    }
    if (i < n) g_scan[i] = sh[tid] - v;   // exclusive within block
    if (tid == 1023) g_bsum[blockIdx.x] = sh[tid];
}

// Phase C: each block scans the (<=128) block sums in smem, then writes
// rowptr & fill with its offset.
__global__ __launch_bounds__(1024) void scanC_k(int n, int nb) {
    __shared__ int sh[128];
    int tid = threadIdx.x;
    if (tid < 128) sh[tid] = (tid < nb) ? g_bsum[tid] : 0;
    __syncthreads();
#pragma unroll
    for (int off = 1; off < 128; off <<= 1) {
        int t = (tid >= off && tid < 128) ? sh[tid - off] : 0;
        __syncthreads();
        if (tid < 128) sh[tid] += t;
        __syncthreads();
    }
    int i = blockIdx.x * 1024 + tid;
    if (i < n) {
        int offb = (blockIdx.x == 0) ? 0 : sh[blockIdx.x - 1];
        int r = g_scan[i] + offb;
        g_rowptr[i] = r;
        g_fill[i]   = r;
    }
    if (blockIdx.x == 0 && tid == 0) g_rowptr[n] = sh[nb - 1];
}

__global__ void scatter_k(const int* __restrict__ src, const int* __restrict__ dst, int e) {
    int i4 = blockIdx.x * blockDim.x + threadIdx.x;
    int base = i4 * 4;
    if (base + 3 < e) {
        int4 d = *(const int4*)(dst + base);
        int4 s = *(const int4*)(src + base);
        int p0 = atomicAdd(&g_fill[d.x], 1);
        int p1 = atomicAdd(&g_fill[d.y], 1);
        int p2 = atomicAdd(&g_fill[d.z], 1);
        int p3 = atomicAdd(&g_fill[d.w], 1);
        g_col[p0] = s.x; g_col[p1] = s.y; g_col[p2] = s.z; g_col[p3] = s.w;
    } else {
        for (int j = base; j < e; j++) {
            int p = atomicAdd(&g_fill[dst[j]], 1);
            g_col[p] = src[j];
        }
    }
}

// ============================================================
// x -> fp16 conversion (once per launch)
// ============================================================
__global__ void cvt_x_k(const float4* __restrict__ x, uint2* __restrict__ o, int n4) {
    int i = blockIdx.x * blockDim.x + threadIdx.x;
    if (i < n4) {
        float4 v = x[i];
        __half2 h0 = __floats2half2_rn(v.x, v.y);
        __half2 h1 = __floats2half2_rn(v.z, v.w);
        uint2 u;
        u.x = *(uint32_t*)&h0;
        u.y = *(uint32_t*)&h1;
        o[i] = u;
    }
}

// ============================================================
// mma / ldmatrix / cp.async helpers
// ============================================================
__device__ __forceinline__ uint32_t smem_u32(const void* p) {
    return (uint32_t)__cvta_generic_to_shared(p);
}

__device__ __forceinline__ void ldsm_x4(uint32_t& r0, uint32_t& r1, uint32_t& r2, uint32_t& r3,
                                        uint32_t a) {
    asm volatile("ldmatrix.sync.aligned.m8n8.x4.shared.b16 {%0,%1,%2,%3}, [%4];"
                 : "=r"(r0), "=r"(r1), "=r"(r2), "=r"(r3) : "r"(a));
}
__device__ __forceinline__ void ldsm_x2(uint32_t& r0, uint32_t& r1, uint32_t a) {
    asm volatile("ldmatrix.sync.aligned.m8n8.x2.shared.b16 {%0,%1}, [%2];"
                 : "=r"(r0), "=r"(r1) : "r"(a));
}
__device__ __forceinline__ void mma_f16(
    float c[4], uint32_t a0, uint32_t a1, uint32_t a2, uint32_t a3,
    uint32_t b0, uint32_t b1)
{
    asm volatile(
        "mma.sync.aligned.m16n8k16.row.col.f32.f16.f16.f32 "
        "{%0,%1,%2,%3}, {%4,%5,%6,%7}, {%8,%9}, {%0,%1,%2,%3};"
        : "+f"(c[0]), "+f"(c[1]), "+f"(c[2]), "+f"(c[3])
        : "r"(a0), "r"(a1), "r"(a2), "r"(a3), "r"(b0), "r"(b1));
}

__device__ __forceinline__ void cp_async16(uint32_t dst, const void* src, int srcbytes) {
    asm volatile("cp.async.cg.shared.global [%0], [%1], 16, %2;"
                 :: "r"(dst), "l"(src), "r"(srcbytes));
}
__device__ __forceinline__ void cp_commit() {
    asm volatile("cp.async.commit_group;" ::: "memory");
}
template <int N>
__device__ __forceinline__ void cp_wait() {
    asm volatile("cp.async.wait_group %0;" :: "n"(N) : "memory");
}

__device__ __forceinline__ __half2 u2h(uint32_t u) { return *(__half2*)&u; }

// ============================================================
// Fused layer GEMM (layers 0/1, agg-first):
//   H = relu( Agg @ Wl + X @ Wr + bias )   (fp16 out)
// BM=128; 512 threads; warp tile M=32 x N=32.
// ============================================================
__global__ __launch_bounds__(512) void gemm_l01(
    const __half* __restrict__ Agg, const __half* __restrict__ X,
    const float* __restrict__ Wl, const float* __restrict__ Wr,
    const float* __restrict__ bias,
    __half* __restrict__ H, int n)
{
    constexpr int DOUT = 128;
    constexpr int BM = 128;
    constexpr int KP = K_DIM + 8;        // 136 halves = 272 B row stride
    constexpr int NF = 4;                // 8-col strips per warp

    extern __shared__ __half smh[];
    __half (*Wt)[DOUT][KP]   = (__half(*)[DOUT][KP])smh;                    // [2][128][KP]
    __half (*As)[2][BM][KP]  = (__half(*)[2][BM][KP])(smh + 2 * DOUT * KP); // [2][2][128][KP]

    const int tid = threadIdx.x;
    const int nTiles = (n + BM - 1) / BM;

    int tile0 = blockIdx.x;
    for (int v = 0; v < 8; v++) {
        int idx = tid + v * 512;
        int which = idx >> 11;
        int rem = idx & 2047;
        int rr  = rem >> 4;
        int ch  = rem & 15;
        int gr  = tile0 * BM + rr;
        bool ok = (tile0 < nTiles) && (gr < n);
        const __half* base = which ? X : Agg;
        const __half* src = ok ? (base + (size_t)gr * K_DIM + ch * 8) : base;
        cp_async16(smem_u32(&As[0][which][rr][ch * 8]), src, ok ? 16 : 0);
    }
    cp_commit();

    for (int w = 0; w < 2; w++) {
        const float* W = w ? Wr : Wl;
#pragma unroll
        for (int v = 0; v < (K_DIM * DOUT / 4) / 512; v++) {
            int idx = tid + v * 512;
            int kk  = idx / (DOUT / 4);
            int n4  = (idx % (DOUT / 4)) * 4;
            float4 bv = *(const float4*)(W + (size_t)kk * DOUT + n4);
            Wt[w][n4 + 0][kk] = __float2half_rn(bv.x);
            Wt[w][n4 + 1][kk] = __float2half_rn(bv.y);
            Wt[w][n4 + 2][kk] = __float2half_rn(bv.z);
            Wt[w][n4 + 3][kk] = __float2half_rn(bv.w);
        }
    }

    const int warp = tid >> 5;
    const int lane = tid & 31;
    const int g    = lane >> 2;
    const int tig  = lane & 3;
    const int rgrp = warp & 3;
    const int nq   = warp >> 2;
    const int wrow = rgrp * 32;
    const int col0 = nq * 32;

    const int a_row0 = wrow + (lane & 15);
    const int a_row1 = wrow + 16 + (lane & 15);
    const int a_koff = (lane >> 4) << 3;
    const int b_row  = (lane & 7);
    const int b_koff = ((lane >> 3) & 1) << 3;

    int buf = 0;
    for (int tile = tile0; tile < nTiles; tile += gridDim.x) {
        int nextTile = tile + gridDim.x;
        if (nextTile < nTiles) {
            for (int v = 0; v < 8; v++) {
                int idx = tid + v * 512;
                int which = idx >> 11;
                int rem = idx & 2047;
                int rr  = rem >> 4;
                int ch  = rem & 15;
                int gr  = nextTile * BM + rr;
                bool ok = (gr < n);
                const __half* base = which ? X : Agg;
                const __half* src = ok ? (base + (size_t)gr * K_DIM + ch * 8) : base;
                cp_async16(smem_u32(&As[buf ^ 1][which][rr][ch * 8]), src, ok ? 16 : 0);
            }
            cp_commit();
            cp_wait<1>();
        } else {
            cp_wait<0>();
        }
        __syncthreads();

        const int row0 = tile * BM;

        float acc[2][NF][4];
#pragma unroll
        for (int at = 0; at < 2; at++)
#pragma unroll
            for (int f = 0; f < NF; f++)
#pragma unroll
                for (int j = 0; j < 4; j++) acc[at][f][j] = 0.f;

#pragma unroll
        for (int kstep = 0; kstep < K_DIM / 16; kstep++) {
            const int kb = kstep * 16;
            {
                uint32_t a0, a1, a2, a3, c0, c1, c2, c3;
                ldsm_x4(a0, a1, a2, a3, smem_u32(&As[buf][0][a_row0][kb + a_koff]));
                ldsm_x4(c0, c1, c2, c3, smem_u32(&As[buf][0][a_row1][kb + a_koff]));
#pragma unroll
                for (int f = 0; f < NF; f++) {
                    uint32_t b0, b1;
                    ldsm_x2(b0, b1, smem_u32(&Wt[0][col0 + f * 8 + b_row][kb + b_koff]));
                    mma_f16(acc[0][f], a0, a1, a2, a3, b0, b1);
                    mma_f16(acc[1][f], c0, c1, c2, c3, b0, b1);
                }
            }
            {
                uint32_t a0, a1, a2, a3, c0, c1, c2, c3;
                ldsm_x4(a0, a1, a2, a3, smem_u32(&As[buf][1][a_row0][kb + a_koff]));
                ldsm_x4(c0, c1, c2, c3, smem_u32(&As[buf][1][a_row1][kb + a_koff]));
#pragma unroll
                for (int f = 0; f < NF; f++) {
                    uint32_t b0, b1;
                    ldsm_x2(b0, b1, smem_u32(&Wt[1][col0 + f * 8 + b_row][kb + b_koff]));
                    mma_f16(acc[0][f], a0, a1, a2, a3, b0, b1);
                    mma_f16(acc[1][f], c0, c1, c2, c3, b0, b1);
                }
            }
        }

#pragma unroll
        for (int at = 0; at < 2; at++) {
            const int r_lo = row0 + wrow + at * 16 + g;
            const int r_hi = r_lo + 8;
#pragma unroll
            for (int f = 0; f < NF; f++) {
                int col = col0 + f * 8 + 2 * tig;
                float bv0 = bias[col];
                float bv1 = bias[col + 1];
                if (r_lo < n) {
                    float o0 = fmaxf(acc[at][f][0] + bv0, 0.f);
                    float o1 = fmaxf(acc[at][f][1] + bv1, 0.f);
                    __half2 h = __floats2half2_rn(o0, o1);
                    *(__half2*)(H + (size_t)r_lo * DOUT + col) = h;
                }
                if (r_hi < n) {
                    float o0 = fmaxf(acc[at][f][2] + bv0, 0.f);
                    float o1 = fmaxf(acc[at][f][3] + bv1, 0.f);
                    __half2 h = __floats2half2_rn(o0, o1);
                    *(__half2*)(H + (size_t)r_hi * DOUT + col) = h;
                }
            }
        }

        __syncthreads();
        buf ^= 1;
    }
}

// ============================================================
// Layer-2 dual GEMM: xl = A @ Wl2 (fp16), xr = A @ Wr2 + b2 (fp32)
// ============================================================
__global__ __launch_bounds__(512) void gemm_h64(
    const __half* __restrict__ A,
    const float* __restrict__ Wl, const float* __restrict__ Wr,
    const float* __restrict__ bias,
    __half* __restrict__ Cl, float* __restrict__ Cr, int n)
{
    constexpr int DOUT = 64;
    constexpr int BM = 128;
    constexpr int KP = K_DIM + 8;
    constexpr int NF = 2;

    extern __shared__ __half smh[];
    __half (*Wt)[DOUT][KP] = (__half(*)[DOUT][KP])smh;
    __half (*As)[BM][KP]   = (__half(*)[BM][KP])(smh + 2 * DOUT * KP);

    const int tid = threadIdx.x;
    const int nTiles = (n + BM - 1) / BM;

    int tile0 = blockIdx.x;
    for (int v = 0; v < 4; v++) {
        int idx = tid + v * 512;
        int rr  = idx >> 4;
        int ch  = idx & 15;
        int gr  = tile0 * BM + rr;
        bool ok = (tile0 < nTiles) && (gr < n);
        const __half* src = ok ? (A + (size_t)gr * K_DIM + ch * 8) : A;
        cp_async16(smem_u32(&As[0][rr][ch * 8]), src, ok ? 16 : 0);
    }
    cp_commit();

    for (int w = 0; w < 2; w++) {
        const float* W = w ? Wr : Wl;
#pragma unroll
        for (int v = 0; v < (K_DIM * DOUT / 4) / 512; v++) {
            int idx = tid + v * 512;
            int kk  = idx / (DOUT / 4);
            int n4  = (idx % (DOUT / 4)) * 4;
            float4 bv = *(const float4*)(W + (size_t)kk * DOUT + n4);
            Wt[w][n4 + 0][kk] = __float2half_rn(bv.x);
            Wt[w][n4 + 1][kk] = __float2half_rn(bv.y);
            Wt[w][n4 + 2][kk] = __float2half_rn(bv.z);
            Wt[w][n4 + 3][kk] = __float2half_rn(bv.w);
        }
    }

    const int warp = tid >> 5;
    const int lane = tid & 31;
    const int g    = lane >> 2;
    const int tig  = lane & 3;
    const int rgrp = warp & 3;
    const int nq   = warp >> 2;
    const int wrow = rgrp * 32;
    const int col0 = nq * 16;

    const int a_row0 = wrow + (lane & 15);
    const int a_row1 = wrow + 16 + (lane & 15);
    const int a_koff = (lane >> 4) << 3;
    const int b_row  = (lane & 7);
    const int b_koff = ((lane >> 3) & 1) << 3;

    int buf = 0;
    for (int tile = tile0; tile < nTiles; tile += gridDim.x) {
        int nextTile = tile + gridDim.x;
        if (nextTile < nTiles) {
            for (int v = 0; v < 4; v++) {
                int idx = tid + v * 512;
                int rr  = idx >> 4;
                int ch  = idx & 15;
                int gr  = nextTile * BM + rr;
                bool ok = (gr < n);
                const __half* src = ok ? (A + (size_t)gr * K_DIM + ch * 8) : A;
                cp_async16(smem_u32(&As[buf ^ 1][rr][ch * 8]), src, ok ? 16 : 0);
            }
            cp_commit();
            cp_wait<1>();
        } else {
            cp_wait<0>();
        }
        __syncthreads();

        const int row0 = tile * BM;

        float acc[2][2][NF][4];
#pragma unroll
        for (int w = 0; w < 2; w++)
#pragma unroll
            for (int at = 0; at < 2; at++)
#pragma unroll
                for (int f = 0; f < NF; f++)
#pragma unroll
                    for (int j = 0; j < 4; j++) acc[w][at][f][j] = 0.f;

#pragma unroll
        for (int kstep = 0; kstep < K_DIM / 16; kstep++) {
            const int kb = kstep * 16;
            uint32_t a0, a1, a2, a3, c0, c1, c2, c3;
            ldsm_x4(a0, a1, a2, a3, smem_u32(&As[buf][a_row0][kb + a_koff]));
            ldsm_x4(c0, c1, c2, c3, smem_u32(&As[buf][a_row1][kb + a_koff]));
#pragma unroll
            for (int wsel = 0; wsel < 2; wsel++) {
#pragma unroll
                for (int f = 0; f < NF; f++) {
                    uint32_t b0, b1;
                    ldsm_x2(b0, b1, smem_u32(&Wt[wsel][col0 + f * 8 + b_row][kb + b_koff]));
                    mma_f16(acc[wsel][0][f], a0, a1, a2, a3, b0, b1);
                    mma_f16(acc[wsel][1][f], c0, c1, c2, c3, b0, b1);
                }
            }
        }

#pragma unroll
        for (int at = 0; at < 2; at++) {
            const int r_lo = row0 + wrow + at * 16 + g;
            const int r_hi = r_lo + 8;
#pragma unroll
            for (int f = 0; f < NF; f++) {
                int col = col0 + f * 8 + 2 * tig;
                if (r_lo < n) {
                    __half2 h = __floats2half2_rn(acc[0][at][f][0], acc[0][at][f][1]);
                    *(__half2*)(Cl + (size_t)r_lo * DOUT + col) = h;
                }
                if (r_hi < n) {
                    __half2 h = __floats2half2_rn(acc[0][at][f][2], acc[0][at][f][3]);
                    *(__half2*)(Cl + (size_t)r_hi * DOUT + col) = h;
                }
                float bv0 = bias[col];
                float bv1 = bias[col + 1];
                if (r_lo < n)
                    *(float2*)(Cr + (size_t)r_lo * DOUT + col) =
                        make_float2(acc[1][at][f][0] + bv0, acc[1][at][f][1] + bv1);
                if (r_hi < n)
                    *(float2*)(Cr + (size_t)r_hi * DOUT + col) =
                        make_float2(acc[1][at][f][2] + bv0, acc[1][at][f][3] + bv1);
            }
        }

        __syncthreads();
        buf ^= 1;
    }
}

// ============================================================
// Pure mean-aggregation (128-dim, fp16 -> fp16), issue-optimized:
// pairwise __hadd2 of two edges (one fp16 rounding), then fp32 accumulate.
// ============================================================
__global__ __launch_bounds__(256) void agg_mean128(
    const __half* __restrict__ xin, __half* __restrict__ out, int n)
{
    int gw   = (blockIdx.x * blockDim.x + threadIdx.x) >> 5;
    int lane = threadIdx.x & 31;
    if (gw >= n) return;

    int beg = g_rowptr[gw];
    int end = g_rowptr[gw + 1];
    float inv = 1.f / fmaxf((float)(end - beg), 1.f);

    const uint2* X = (const uint2*)xin;
    float ax = 0.f, ay = 0.f, az = 0.f, aw = 0.f;
    float bx = 0.f, by = 0.f, bz = 0.f, bw = 0.f;

    int e = beg;
    for (; e + 8 <= end; e += 8) {
        int s0 = g_col[e + 0], s1 = g_col[e + 1], s2 = g_col[e + 2], s3 = g_col[e + 3];
        int s4 = g_col[e + 4], s5 = g_col[e + 5], s6 = g_col[e + 6], s7 = g_col[e + 7];
        uint2 v0 = X[(size_t)s0 * 32 + lane];
        uint2 v1 = X[(size_t)s1 * 32 + lane];
        uint2 v2 = X[(size_t)s2 * 32 + lane];
        uint2 v3 = X[(size_t)s3 * 32 + lane];
        uint2 v4 = X[(size_t)s4 * 32 + lane];
        uint2 v5 = X[(size_t)s5 * 32 + lane];
        uint2 v6 = X[(size_t)s6 * 32 + lane];
        uint2 v7 = X[(size_t)s7 * 32 + lane];
        __half2 p, q;
        float2 f;
        p = __hadd2(u2h(v0.x), u2h(v1.x));
        q = __hadd2(u2h(v0.y), u2h(v1.y));
        f = __half22float2(p); ax += f.x; ay += f.y;
        f = __half22float2(q); az += f.x; aw += f.y;
        p = __hadd2(u2h(v2.x), u2h(v3.x));
        q = __hadd2(u2h(v2.y), u2h(v3.y));
        f = __half22float2(p); bx += f.x; by += f.y;
        f = __half22float2(q); bz += f.x; bw += f.y;
        p = __hadd2(u2h(v4.x), u2h(v5.x));
        q = __hadd2(u2h(v4.y), u2h(v5.y));
        f = __half22float2(p); ax += f.x; ay += f.y;
        f = __half22float2(q); az += f.x; aw += f.y;
        p = __hadd2(u2h(v6.x), u2h(v7.x));
        q = __hadd2(u2h(v6.y), u2h(v7.y));
        f = __half22float2(p); bx += f.x; by += f.y;
        f = __half22float2(q); bz += f.x; bw += f.y;
    }
    for (; e + 2 <= end; e += 2) {
        int s0 = g_col[e], s1 = g_col[e + 1];
        uint2 v0 = X[(size_t)s0 * 32 + lane];
        uint2 v1 = X[(size_t)s1 * 32 + lane];
        __half2 p = __hadd2(u2h(v0.x), u2h(v1.x));
        __half2 q = __hadd2(u2h(v0.y), u2h(v1.y));
        float2 f;
        f = __half22float2(p); ax += f.x; ay += f.y;
        f = __half22float2(q); az += f.x; aw += f.y;
    }
    for (; e < end; e++) {
        int s = g_col[e];
        uint2 v = X[(size_t)s * 32 + lane];
        float2 f;
        f = __half22float2(u2h(v.x)); ax += f.x; ay += f.y;
        f = __half22float2(u2h(v.y)); az += f.x; aw += f.y;
    }

    float ox = (ax + bx) * inv;
    float oy = (ay + by) * inv;
    float oz = (az + bz) * inv;
    float ow = (aw + bw) * inv;
    __half2 h0 = __floats2half2_rn(ox, oy);
    __half2 h1 = __floats2half2_rn(oz, ow);
    uint2 u;
    u.x = *(uint32_t*)&h0;
    u.y = *(uint32_t*)&h1;
    ((uint2*)out)[(size_t)gw * 32 + lane] = u;
}

// ============================================================
// Layer-2 aggregation + epilogue (64-dim): out = mean(xl[s]) + xr (fp32)
// Pairwise __hadd2 pre-reduction.
// ============================================================
__global__ __launch_bounds__(256) void agg_ep64h(
    const __half* __restrict__ xl, const float* __restrict__ xr,
    float* __restrict__ out, int n)
{
    int gw   = (blockIdx.x * blockDim.x + threadIdx.x) >> 5;
    int lane = threadIdx.x & 31;
    if (gw >= n) return;

    int beg = g_rowptr[gw];
    int end = g_rowptr[gw + 1];
    float inv = 1.f / fmaxf((float)(end - beg), 1.f);

    const uint32_t* X = (const uint32_t*)xl;
    float ax = 0.f, ay = 0.f, bx = 0.f, by = 0.f;

    int e = beg;
    for (; e + 8 <= end; e += 8) {
        int s0 = g_col[e + 0], s1 = g_col[e + 1], s2 = g_col[e + 2], s3 = g_col[e + 3];
        int s4 = g_col[e + 4], s5 = g_col[e + 5], s6 = g_col[e + 6], s7 = g_col[e + 7];
        uint32_t v0 = X[(size_t)s0 * 32 + lane];
        uint32_t v1 = X[(size_t)s1 * 32 + lane];
        uint32_t v2 = X[(size_t)s2 * 32 + lane];
        uint32_t v3 = X[(size_t)s3 * 32 + lane];
        uint32_t v4 = X[(size_t)s4 * 32 + lane];
        uint32_t v5 = X[(size_t)s5 * 32 + lane];
        uint32_t v6 = X[(size_t)s6 * 32 + lane];
        uint32_t v7 = X[(size_t)s7 * 32 + lane];
        __half2 p;
        float2 f;
        p = __hadd2(u2h(v0), u2h(v1)); f = __half22float2(p); ax += f.x; ay += f.y;
        p = __hadd2(u2h(v2), u2h(v3)); f = __half22float2(p); bx += f.x; by += f.y;
        p = __hadd2(u2h(v4), u2h(v5)); f = __half22float2(p); ax += f.x; ay += f.y;
        p = __hadd2(u2h(v6), u2h(v7)); f = __half22float2(p); bx += f.x; by += f.y;
    }
    for (; e + 2 <= end; e += 2) {
        int s0 = g_col[e], s1 = g_col[e + 1];
        __half2 p = __hadd2(u2h(X[(size_t)s0 * 32 + lane]), u2h(X[(size_t)s1 * 32 + lane]));
        float2 f = __half22float2(p);
        ax += f.x; ay += f.y;
    }
    for (; e < end; e++) {
        int s = g_col[e];
        float2 f = __half22float2(u2h(X[(size_t)s * 32 + lane]));
        ax += f.x; ay += f.y;
    }

    float2 r = ((const float2*)xr)[(size_t)gw * 32 + lane];
    float2 o;
    o.x = (ax + bx) * inv + r.x;
    o.y = (ay + by) * inv + r.y;
    ((float2*)out)[(size_t)gw * 32 + lane] = o;
}

// ============================================================
// Launch — single stream.
// ============================================================
extern "C" void kernel_launch(void* const* d_in, const int* in_sizes, int n_in,
                              void* d_out, int out_size)
{
    const float* x   = (const float*)d_in[0];
    const int*   ei  = (const int*)d_in[1];
    const float* Wl0 = (const float*)d_in[2];
    const float* Wr0 = (const float*)d_in[3];
    const float* b0  = (const float*)d_in[4];
    const float* Wl1 = (const float*)d_in[5];
    const float* Wr1 = (const float*)d_in[6];
    const float* b1  = (const float*)d_in[7];
    const float* Wl2 = (const float*)d_in[8];
    const float* Wr2 = (const float*)d_in[9];
    const float* b2  = (const float*)d_in[10];

    const int n = in_sizes[0] / 128;
    const int e = in_sizes[1] / 2;
    const int* src = ei;
    const int* dst = ei + e;

    void *px16, *pagg, *pha, *phb, *pxl, *pxr, *pdeg;
    cudaGetSymbolAddress(&px16, g_x16);
    cudaGetSymbolAddress(&pagg, g_agg);
    cudaGetSymbolAddress(&pha, g_ha);
    cudaGetSymbolAddress(&phb, g_hb);
    cudaGetSymbolAddress(&pxl, g_xl);
    cudaGetSymbolAddress(&pxr, g_xr);
    cudaGetSymbolAddress(&pdeg, g_deg);
    __half* f_x16 = (__half*)px16;
    __half* f_agg = (__half*)pagg;
    __half* f_ha  = (__half*)pha;
    __half* f_hb  = (__half*)phb;
    __half* f_xl  = (__half*)pxl;
    float*  f_xr  = (float*)pxr;

    // smem (bytes)
    constexpr int KP = K_DIM + 8;
    constexpr int SM_L01 = (2 * 128 * KP + 2 * 2 * 128 * KP) * 2;  // 208896
    constexpr int SM_H64 = (2 * 64 * KP + 2 * 128 * KP) * 2;       // 104448
    static bool attr_set = false;
    if (!attr_set) {
        cudaFuncSetAttribute(gemm_l01, cudaFuncAttributeMaxDynamicSharedMemorySize, SM_L01);
        cudaFuncSetAttribute(gemm_h64, cudaFuncAttributeMaxDynamicSharedMemorySize, SM_H64);
        attr_set = true;
    }

    const int NSM = 148;
    const int agg_blocks = (n + 7) / 8;
    const int nb = (n + 1023) / 1024;

    // x -> fp16
    cvt_x_k<<<(n * 32 + 255) / 256, 256>>>((const float4*)x, (uint2*)f_x16, n * 32);

    // CSR build (round-11 proven path)
    cudaMemsetAsync(pdeg, 0, (size_t)n * sizeof(int));
    hist_k<<<((e + 3) / 4 + 255) / 256, 256>>>(dst, e);
    scanA_k<<<nb, 1024>>>(n);
    scanC_k<<<nb, 1024>>>(n, nb);
    scatter_k<<<((e + 3) / 4 + 255) / 256, 256>>>(src, dst, e);

    // Layer 0: aggx = mean(x16); h1 = relu(aggx@Wl0 + x16@Wr0 + b0)
    agg_mean128<<<agg_blocks, 256>>>(f_x16, f_agg, n);
    gemm_l01<<<NSM, 512, SM_L01>>>(f_agg, f_x16, Wl0, Wr0, b0, f_ha, n);

    // Layer 1
    agg_mean128<<<agg_blocks, 256>>>(f_ha, f_agg, n);
    gemm_l01<<<NSM, 512, SM_L01>>>(f_agg, f_ha, Wl1, Wr1, b1, f_hb, n);

    // Layer 2 (transform-first, DOUT=64): xl = h2@Wl2, xr = h2@Wr2 + b2
    gemm_h64<<<NSM, 512, SM_H64>>>(f_hb, Wl2, Wr2, b2, f_xl, f_xr, n);
    agg_ep64h<<<agg_blocks, 256>>>(f_xl, f_xr, (float*)d_out, n);
}

// round 14
// speedup vs baseline: 1.4016x; 1.0016x over previous
#include <cuda_runtime.h>
#include <cuda_fp16.h>
#include <cstdint>
#include <cstddef>

// Problem constants (match reference)
#define NMAX 100000
#define EMAX 1600000
#define K_DIM 128

// ---- Scratch (device globals; no allocations allowed) ----
__device__ int    g_deg[NMAX];
__device__ int    g_rowptr[NMAX + 1];
__device__ int    g_fill[NMAX];
__device__ int    g_col[EMAX];
__device__ int    g_scan[NMAX];
__device__ int    g_bsum[128];
__device__ __half g_x16[(size_t)NMAX * 128];  // fp16 copy of input x
__device__ __half g_agg[(size_t)NMAX * 128];  // mean-aggregated features (fp16)
__device__ __half g_ha[(size_t)NMAX * 128];   // layer-0 output (fp16)
__device__ __half g_hb[(size_t)NMAX * 128];   // layer-1 output (fp16)
__device__ __half g_xl[(size_t)NMAX * 64];    // layer-2 aggregated-path (fp16)
__device__ float  g_xr[(size_t)NMAX * 64];    // layer-2 self-path (fp32)

// ============================================================
// CSR build (counting sort by dst), rebuilt every launch
// ============================================================
__global__ void hist_k(const int* __restrict__ dst, int e) {
    int i4 = blockIdx.x * blockDim.x + threadIdx.x;
    int base = i4 * 4;
    if (base + 3 < e) {
        int4 d = *(const int4*)(dst + base);
        atomicAdd(&g_deg[d.x], 1);
        atomicAdd(&g_deg[d.y], 1);
        atomicAdd(&g_deg[d.z], 1);
        atomicAdd(&g_deg[d.w], 1);
    } else {
        for (int j = base; j < e; j++) atomicAdd(&g_deg[dst[j]], 1);
    }
}

// Phase A: per-block inclusive scan of 1024 deg entries
__global__ __launch_bounds__(1024) void scanA_k(int n) {
    __shared__ int sh[1024];
    int tid = threadIdx.x;
    int i = blockIdx.x * 1024 + tid;
    int v = (i < n) ? g_deg[i] : 0;
    sh[tid] = v;
    __syncthreads();
#pragma unroll
    for (int off = 1; off < 1024; off <<= 1) {
        int t = (tid >= off) ? sh[tid - off] : 0;
        __syncthreads();
        sh[tid] += t;
        __syncthreads();
    }
    if (i < n) g_scan[i] = sh[tid] - v;   // exclusive within block
    if (tid == 1023) g_bsum[blockIdx.x] = sh[tid];
}

// Phase C: each block scans the (<=128) block sums in smem, then writes
// rowptr & fill with its offset.
__global__ __launch_bounds__(1024) void scanC_k(int n, int nb) {
    __shared__ int sh[128];
    int tid = threadIdx.x;
    if (tid < 128) sh[tid] = (tid < nb) ? g_bsum[tid] : 0;
    __syncthreads();
#pragma unroll
    for (int off = 1; off < 128; off <<= 1) {
        int t = (tid >= off && tid < 128) ? sh[tid - off] : 0;
        __syncthreads();
        if (tid < 128) sh[tid] += t;
        __syncthreads();
    }
    int i = blockIdx.x * 1024 + tid;
    if (i < n) {
        int offb = (blockIdx.x == 0) ? 0 : sh[blockIdx.x - 1];
        int r = g_scan[i] + offb;
        g_rowptr[i] = r;
        g_fill[i]   = r;
    }
    if (blockIdx.x == 0 && tid == 0) g_rowptr[n] = sh[nb - 1];
}

__global__ void scatter_k(const int* __restrict__ src, const int* __restrict__ dst, int e) {
    int i4 = blockIdx.x * blockDim.x + threadIdx.x;
    int base = i4 * 4;
    if (base + 3 < e) {
        int4 d = *(const int4*)(dst + base);
        int4 s = *(const int4*)(src + base);
        int p0 = atomicAdd(&g_fill[d.x], 1);
        int p1 = atomicAdd(&g_fill[d.y], 1);
        int p2 = atomicAdd(&g_fill[d.z], 1);
        int p3 = atomicAdd(&g_fill[d.w], 1);
        g_col[p0] = s.x; g_col[p1] = s.y; g_col[p2] = s.z; g_col[p3] = s.w;
    } else {
        for (int j = base; j < e; j++) {
            int p = atomicAdd(&g_fill[dst[j]], 1);
            g_col[p] = src[j];
        }
    }
}

// ============================================================
// x -> fp16 conversion (once per launch; forked onto stream 2)
// ============================================================
__global__ void cvt_x_k(const float4* __restrict__ x, uint2* __restrict__ o, int n4) {
    int i = blockIdx.x * blockDim.x + threadIdx.x;
    if (i < n4) {
        float4 v = x[i];
        __half2 h0 = __floats2half2_rn(v.x, v.y);
        __half2 h1 = __floats2half2_rn(v.z, v.w);
        uint2 u;
        u.x = *(uint32_t*)&h0;
        u.y = *(uint32_t*)&h1;
        o[i] = u;
    }
}

// ============================================================
// mma / ldmatrix / cp.async helpers
// ============================================================
__device__ __forceinline__ uint32_t smem_u32(const void* p) {
    return (uint32_t)__cvta_generic_to_shared(p);
}

__device__ __forceinline__ void ldsm_x4(uint32_t& r0, uint32_t& r1, uint32_t& r2, uint32_t& r3,
                                        uint32_t a) {
    asm volatile("ldmatrix.sync.aligned.m8n8.x4.shared.b16 {%0,%1,%2,%3}, [%4];"
                 : "=r"(r0), "=r"(r1), "=r"(r2), "=r"(r3) : "r"(a));
}
__device__ __forceinline__ void mma_f16(
    float c[4], uint32_t a0, uint32_t a1, uint32_t a2, uint32_t a3,
    uint32_t b0, uint32_t b1)
{
    asm volatile(
        "mma.sync.aligned.m16n8k16.row.col.f32.f16.f16.f32 "
        "{%0,%1,%2,%3}, {%4,%5,%6,%7}, {%8,%9}, {%0,%1,%2,%3};"
        : "+f"(c[0]), "+f"(c[1]), "+f"(c[2]), "+f"(c[3])
        : "r"(a0), "r"(a1), "r"(a2), "r"(a3), "r"(b0), "r"(b1));
}

__device__ __forceinline__ void cp_async16(uint32_t dst, const void* src, int srcbytes) {
    asm volatile("cp.async.cg.shared.global [%0], [%1], 16, %2;"
                 :: "r"(dst), "l"(src), "r"(srcbytes));
}
__device__ __forceinline__ void cp_commit() {
    asm volatile("cp.async.commit_group;" ::: "memory");
}
template <int N>
__device__ __forceinline__ void cp_wait() {
    asm volatile("cp.async.wait_group %0;" :: "n"(N) : "memory");
}

__device__ __forceinline__ __half2 u2h(uint32_t u) { return *(__half2*)&u; }

// ============================================================
// Fused layer GEMM (layers 0/1, agg-first):
//   H = relu( Agg @ Wl + X @ Wr + bias )   (fp16 out)
// BM=128; 512 threads; warp tile M=32 x N=32. B frags via ldsm.x4
// (two 8-col strips per instruction).
// ============================================================
__global__ __launch_bounds__(512) void gemm_l01(
    const __half* __restrict__ Agg, const __half* __restrict__ X,
    const float* __restrict__ Wl, const float* __restrict__ Wr,
    const float* __restrict__ bias,
    __half* __restrict__ H, int n)
{
    constexpr int DOUT = 128;
    constexpr int BM = 128;
    constexpr int KP = K_DIM + 8;        // 136 halves = 272 B row stride
    constexpr int NF = 4;                // 8-col strips per warp

    extern __shared__ __half smh[];
    __half (*Wt)[DOUT][KP]   = (__half(*)[DOUT][KP])smh;                    // [2][128][KP]
    __half (*As)[2][BM][KP]  = (__half(*)[2][BM][KP])(smh + 2 * DOUT * KP); // [2][2][128][KP]

    const int tid = threadIdx.x;
    const int nTiles = (n + BM - 1) / BM;

    int tile0 = blockIdx.x;
    for (int v = 0; v < 8; v++) {
        int idx = tid + v * 512;
        int which = idx >> 11;
        int rem = idx & 2047;
        int rr  = rem >> 4;
        int ch  = rem & 15;
        int gr  = tile0 * BM + rr;
        bool ok = (tile0 < nTiles) && (gr < n);
        const __half* base = which ? X : Agg;
        const __half* src = ok ? (base + (size_t)gr * K_DIM + ch * 8) : base;
        cp_async16(smem_u32(&As[0][which][rr][ch * 8]), src, ok ? 16 : 0);
    }
    cp_commit();

    for (int w = 0; w < 2; w++) {
        const float* W = w ? Wr : Wl;
#pragma unroll
        for (int v = 0; v < (K_DIM * DOUT / 4) / 512; v++) {
            int idx = tid + v * 512;
            int kk  = idx / (DOUT / 4);
            int n4  = (idx % (DOUT / 4)) * 4;
            float4 bv = *(const float4*)(W + (size_t)kk * DOUT + n4);
            Wt[w][n4 + 0][kk] = __float2half_rn(bv.x);
            Wt[w][n4 + 1][kk] = __float2half_rn(bv.y);
            Wt[w][n4 + 2][kk] = __float2half_rn(bv.z);
            Wt[w][n4 + 3][kk] = __float2half_rn(bv.w);
        }
    }

    const int warp = tid >> 5;
    const int lane = tid & 31;
    const int g    = lane >> 2;
    const int tig  = lane & 3;
    const int rgrp = warp & 3;
    const int nq   = warp >> 2;
    const int wrow = rgrp * 32;
    const int col0 = nq * 32;

    const int a_row0 = wrow + (lane & 15);
    const int a_row1 = wrow + 16 + (lane & 15);
    const int a_koff = (lane >> 4) << 3;
    // B x4 addressing: lanes 0-7 -> (strip f, k lo), 8-15 -> (strip f, k hi),
    // 16-23 -> (strip f+1, k lo), 24-31 -> (strip f+1, k hi)
    const int b_row4 = ((lane >> 4) << 3) + (lane & 7);
    const int b_koff = ((lane >> 3) & 1) << 3;

    int buf = 0;
    for (int tile = tile0; tile < nTiles; tile += gridDim.x) {
        int nextTile = tile + gridDim.x;
        if (nextTile < nTiles) {
            for (int v = 0; v < 8; v++) {
                int idx = tid + v * 512;
                int which = idx >> 11;
                int rem = idx & 2047;
                int rr  = rem >> 4;
                int ch  = rem & 15;
                int gr  = nextTile * BM + rr;
                bool ok = (gr < n);
                const __half* base = which ? X : Agg;
                const __half* src = ok ? (base + (size_t)gr * K_DIM + ch * 8) : base;
                cp_async16(smem_u32(&As[buf ^ 1][which][rr][ch * 8]), src, ok ? 16 : 0);
            }
            cp_commit();
            cp_wait<1>();
        } else {
            cp_wait<0>();
        }
        __syncthreads();

        const int row0 = tile * BM;

        float acc[2][NF][4];
#pragma unroll
        for (int at = 0; at < 2; at++)
#pragma unroll
            for (int f = 0; f < NF; f++)
#pragma unroll
                for (int j = 0; j < 4; j++) acc[at][f][j] = 0.f;

#pragma unroll
        for (int kstep = 0; kstep < K_DIM / 16; kstep++) {
            const int kb = kstep * 16;
#pragma unroll
            for (int wsel = 0; wsel < 2; wsel++) {
                uint32_t a0, a1, a2, a3, c0, c1, c2, c3;
                ldsm_x4(a0, a1, a2, a3, smem_u32(&As[buf][wsel][a_row0][kb + a_koff]));
                ldsm_x4(c0, c1, c2, c3, smem_u32(&As[buf][wsel][a_row1][kb + a_koff]));
#pragma unroll
                for (int f = 0; f < NF; f += 2) {
                    uint32_t b0, b1, b2, b3;
                    ldsm_x4(b0, b1, b2, b3,
                            smem_u32(&Wt[wsel][col0 + f * 8 + b_row4][kb + b_koff]));
                    mma_f16(acc[0][f],     a0, a1, a2, a3, b0, b1);
                    mma_f16(acc[1][f],     c0, c1, c2, c3, b0, b1);
                    mma_f16(acc[0][f + 1], a0, a1, a2, a3, b2, b3);
                    mma_f16(acc[1][f + 1], c0, c1, c2, c3, b2, b3);
                }
            }
        }

#pragma unroll
        for (int at = 0; at < 2; at++) {
            const int r_lo = row0 + wrow + at * 16 + g;
            const int r_hi = r_lo + 8;
#pragma unroll
            for (int f = 0; f < NF; f++) {
                int col = col0 + f * 8 + 2 * tig;
                float bv0 = bias[col];
                float bv1 = bias[col + 1];
                if (r_lo < n) {
                    float o0 = fmaxf(acc[at][f][0] + bv0, 0.f);
                    float o1 = fmaxf(acc[at][f][1] + bv1, 0.f);
                    __half2 h = __floats2half2_rn(o0, o1);
                    *(__half2*)(H + (size_t)r_lo * DOUT + col) = h;
                }
                if (r_hi < n) {
                    float o0 = fmaxf(acc[at][f][2] + bv0, 0.f);
                    float o1 = fmaxf(acc[at][f][3] + bv1, 0.f);
                    __half2 h = __floats2half2_rn(o0, o1);
                    *(__half2*)(H + (size_t)r_hi * DOUT + col) = h;
                }
            }
        }

        __syncthreads();
        buf ^= 1;
    }
}

// ============================================================
// Layer-2 dual GEMM: xl = A @ Wl2 (fp16), xr = A @ Wr2 + b2 (fp32)
// B frags via ldsm.x4 (both strips of the 16-col warp tile at once).
// ============================================================
__global__ __launch_bounds__(512) void gemm_h64(
    const __half* __restrict__ A,
    const float* __restrict__ Wl, const float* __restrict__ Wr,
    const float* __restrict__ bias,
    __half* __restrict__ Cl, float* __restrict__ Cr, int n)
{
    constexpr int DOUT = 64;
    constexpr int BM = 128;
    constexpr int KP = K_DIM + 8;
    constexpr int NF = 2;

    extern __shared__ __half smh[];
    __half (*Wt)[DOUT][KP] = (__half(*)[DOUT][KP])smh;
    __half (*As)[BM][KP]   = (__half(*)[BM][KP])(smh + 2 * DOUT * KP);

    const int tid = threadIdx.x;
    const int nTiles = (n + BM - 1) / BM;

    int tile0 = blockIdx.x;
    for (int v = 0; v < 4; v++) {
        int idx = tid + v * 512;
        int rr  = idx >> 4;
        int ch  = idx & 15;
        int gr  = tile0 * BM + rr;
        bool ok = (tile0 < nTiles) && (gr < n);
        const __half* src = ok ? (A + (size_t)gr * K_DIM + ch * 8) : A;
        cp_async16(smem_u32(&As[0][rr][ch * 8]), src, ok ? 16 : 0);
    }
    cp_commit();

    for (int w = 0; w < 2; w++) {
        const float* W = w ? Wr : Wl;
#pragma unroll
        for (int v = 0; v < (K_DIM * DOUT / 4) / 512; v++) {
            int idx = tid + v * 512;
            int kk  = idx / (DOUT / 4);
            int n4  = (idx % (DOUT / 4)) * 4;
            float4 bv = *(const float4*)(W + (size_t)kk * DOUT + n4);
            Wt[w][n4 + 0][kk] = __float2half_rn(bv.x);
            Wt[w][n4 + 1][kk] = __float2half_rn(bv.y);
            Wt[w][n4 + 2][kk] = __float2half_rn(bv.z);
            Wt[w][n4 + 3][kk] = __float2half_rn(bv.w);
        }
    }

    const int warp = tid >> 5;
    const int lane = tid & 31;
    const int g    = lane >> 2;
    const int tig  = lane & 3;
    const int rgrp = warp & 3;
    const int nq   = warp >> 2;
    const int wrow = rgrp * 32;
    const int col0 = nq * 16;

    const int a_row0 = wrow + (lane & 15);
    const int a_row1 = wrow + 16 + (lane & 15);
    const int a_koff = (lane >> 4) << 3;
    const int b_row4 = ((lane >> 4) << 3) + (lane & 7);
    const int b_koff = ((lane >> 3) & 1) << 3;

    int buf = 0;
    for (int tile = tile0; tile < nTiles; tile += gridDim.x) {
        int nextTile = tile + gridDim.x;
        if (nextTile < nTiles) {
            for (int v = 0; v < 4; v++) {
                int idx = tid + v * 512;
                int rr  = idx >> 4;
                int ch  = idx & 15;
                int gr  = nextTile * BM + rr;
                bool ok = (gr < n);
                const __half* src = ok ? (A + (size_t)gr * K_DIM + ch * 8) : A;
                cp_async16(smem_u32(&As[buf ^ 1][rr][ch * 8]), src, ok ? 16 : 0);
            }
            cp_commit();
            cp_wait<1>();
        } else {
            cp_wait<0>();
        }
        __syncthreads();

        const int row0 = tile * BM;

        float acc[2][2][NF][4];
#pragma unroll
        for (int w = 0; w < 2; w++)
#pragma unroll
            for (int at = 0; at < 2; at++)
#pragma unroll
                for (int f = 0; f < NF; f++)
#pragma unroll
                    for (int j = 0; j < 4; j++) acc[w][at][f][j] = 0.f;

#pragma unroll
        for (int kstep = 0; kstep < K_DIM / 16; kstep++) {
            const int kb = kstep * 16;
            uint32_t a0, a1, a2, a3, c0, c1, c2, c3;
            ldsm_x4(a0, a1, a2, a3, smem_u32(&As[buf][a_row0][kb + a_koff]));
            ldsm_x4(c0, c1, c2, c3, smem_u32(&As[buf][a_row1][kb + a_koff]));
#pragma unroll
            for (int wsel = 0; wsel < 2; wsel++) {
                uint32_t b0, b1, b2, b3;
                ldsm_x4(b0, b1, b2, b3,
                        smem_u32(&Wt[wsel][col0 + b_row4][kb + b_koff]));
                mma_f16(acc[wsel][0][0], a0, a1, a2, a3, b0, b1);
                mma_f16(acc[wsel][1][0], c0, c1, c2, c3, b0, b1);
                mma_f16(acc[wsel][0][1], a0, a1, a2, a3, b2, b3);
                mma_f16(acc[wsel][1][1], c0, c1, c2, c3, b2, b3);
            }
        }

#pragma unroll
        for (int at = 0; at < 2; at++) {
            const int r_lo = row0 + wrow + at * 16 + g;
            const int r_hi = r_lo + 8;
#pragma unroll
            for (int f = 0; f < NF; f++) {
                int col = col0 + f * 8 + 2 * tig;
                if (r_lo < n) {
                    __half2 h = __floats2half2_rn(acc[0][at][f][0], acc[0][at][f][1]);
                    *(__half2*)(Cl + (size_t)r_lo * DOUT + col) = h;
                }
                if (r_hi < n) {
                    __half2 h = __floats2half2_rn(acc[0][at][f][2], acc[0][at][f][3]);
                    *(__half2*)(Cl + (size_t)r_hi * DOUT + col) = h;
                }
                float bv0 = bias[col];
                float bv1 = bias[col + 1];
                if (r_lo < n)
                    *(float2*)(Cr + (size_t)r_lo * DOUT + col) =
                        make_float2(acc[1][at][f][0] + bv0, acc[1][at][f][1] + bv1);
                if (r_hi < n)
                    *(float2*)(Cr + (size_t)r_hi * DOUT + col) =
                        make_float2(acc[1][at][f][2] + bv0, acc[1][at][f][3] + bv1);
            }
        }

        __syncthreads();
        buf ^= 1;
    }
}

// ============================================================
// Pure mean-aggregation (128-dim, fp16 -> fp16):
// 4-edge fp16 tree (2 roundings), then fp32 accumulate.
// ============================================================
__global__ __launch_bounds__(256) void agg_mean128(
    const __half* __restrict__ xin, __half* __restrict__ out, int n)
{
    int gw   = (blockIdx.x * blockDim.x + threadIdx.x) >> 5;
    int lane = threadIdx.x & 31;
    if (gw >= n) return;

    int beg = g_rowptr[gw];
    int end = g_rowptr[gw + 1];
    float inv = 1.f / fmaxf((float)(end - beg), 1.f);

    const uint2* X = (const uint2*)xin;
    float ax = 0.f, ay = 0.f, az = 0.f, aw = 0.f;
    float bx = 0.f, by = 0.f, bz = 0.f, bw = 0.f;

    int e = beg;
    for (; e + 8 <= end; e += 8) {
        int s0 = g_col[e + 0], s1 = g_col[e + 1], s2 = g_col[e + 2], s3 = g_col[e + 3];
        int s4 = g_col[e + 4], s5 = g_col[e + 5], s6 = g_col[e + 6], s7 = g_col[e + 7];
        uint2 v0 = X[(size_t)s0 * 32 + lane];
        uint2 v1 = X[(size_t)s1 * 32 + lane];
        uint2 v2 = X[(size_t)s2 * 32 + lane];
        uint2 v3 = X[(size_t)s3 * 32 + lane];
        uint2 v4 = X[(size_t)s4 * 32 + lane];
        uint2 v5 = X[(size_t)s5 * 32 + lane];
        uint2 v6 = X[(size_t)s6 * 32 + lane];
        uint2 v7 = X[(size_t)s7 * 32 + lane];
        __half2 p0, p1, q0, q1;
        float2 f;
        // edges 0-3 -> (ax..aw)
        p0 = __hadd2(u2h(v0.x), u2h(v1.x));
        p1 = __hadd2(u2h(v2.x), u2h(v3.x));
        q0 = __hadd2(u2h(v0.y), u2h(v1.y));
        q1 = __hadd2(u2h(v2.y), u2h(v3.y));
        p0 = __hadd2(p0, p1);
        q0 = __hadd2(q0, q1);
        f = __half22float2(p0); ax += f.x; ay += f.y;
        f = __half22float2(q0); az += f.x; aw += f.y;
        // edges 4-7 -> (bx..bw)
        p0 = __hadd2(u2h(v4.x), u2h(v5.x));
        p1 = __hadd2(u2h(v6.x), u2h(v7.x));
        q0 = __hadd2(u2h(v4.y), u2h(v5.y));
        q1 = __hadd2(u2h(v6.y), u2h(v7.y));
        p0 = __hadd2(p0, p1);
        q0 = __hadd2(q0, q1);
        f = __half22float2(p0); bx += f.x; by += f.y;
        f = __half22float2(q0); bz += f.x; bw += f.y;
    }
    for (; e + 2 <= end; e += 2) {
        int s0 = g_col[e], s1 = g_col[e + 1];
        uint2 v0 = X[(size_t)s0 * 32 + lane];
        uint2 v1 = X[(size_t)s1 * 32 + lane];
        __half2 p = __hadd2(u2h(v0.x), u2h(v1.x));
        __half2 q = __hadd2(u2h(v0.y), u2h(v1.y));
        float2 f;
        f = __half22float2(p); ax += f.x; ay += f.y;
        f = __half22float2(q); az += f.x; aw += f.y;
    }
    for (; e < end; e++) {
        int s = g_col[e];
        uint2 v = X[(size_t)s * 32 + lane];
        float2 f;
        f = __half22float2(u2h(v.x)); ax += f.x; ay += f.y;
        f = __half22float2(u2h(v.y)); az += f.x; aw += f.y;
    }

    float ox = (ax + bx) * inv;
    float oy = (ay + by) * inv;
    float oz = (az + bz) * inv;
    float ow = (aw + bw) * inv;
    __half2 h0 = __floats2half2_rn(ox, oy);
    __half2 h1 = __floats2half2_rn(oz, ow);
    uint2 u;
    u.x = *(uint32_t*)&h0;
    u.y = *(uint32_t*)&h1;
    ((uint2*)out)[(size_t)gw * 32 + lane] = u;
}

// ============================================================
// Layer-2 aggregation + epilogue (64-dim): out = mean(xl[s]) + xr (fp32)
// 4-edge fp16 tree pre-reduction.
// ============================================================
__global__ __launch_bounds__(256) void agg_ep64h(
    const __half* __restrict__ xl, const float* __restrict__ xr,
    float* __restrict__ out, int n)
{
    int gw   = (blockIdx.x * blockDim.x + threadIdx.x) >> 5;
    int lane = threadIdx.x & 31;
    if (gw >= n) return;

    int beg = g_rowptr[gw];
    int end = g_rowptr[gw + 1];
    float inv = 1.f / fmaxf((float)(end - beg), 1.f);

    const uint32_t* X = (const uint32_t*)xl;
    float ax = 0.f, ay = 0.f, bx = 0.f, by = 0.f;

    int e = beg;
    for (; e + 8 <= end; e += 8) {
        int s0 = g_col[e + 0], s1 = g_col[e + 1], s2 = g_col[e + 2], s3 = g_col[e + 3];
        int s4 = g_col[e + 4], s5 = g_col[e + 5], s6 = g_col[e + 6], s7 = g_col[e + 7];
        uint32_t v0 = X[(size_t)s0 * 32 + lane];
        uint32_t v1 = X[(size_t)s1 * 32 + lane];
        uint32_t v2 = X[(size_t)s2 * 32 + lane];
        uint32_t v3 = X[(size_t)s3 * 32 + lane];
        uint32_t v4 = X[(size_t)s4 * 32 + lane];
        uint32_t v5 = X[(size_t)s5 * 32 + lane];
        uint32_t v6 = X[(size_t)s6 * 32 + lane];
        uint32_t v7 = X[(size_t)s7 * 32 + lane];
        __half2 p0, p1;
        float2 f;
        p0 = __hadd2(u2h(v0), u2h(v1));
        p1 = __hadd2(u2h(v2), u2h(v3));
        p0 = __hadd2(p0, p1);
        f = __half22float2(p0); ax += f.x; ay += f.y;
        p0 = __hadd2(u2h(v4), u2h(v5));
        p1 = __hadd2(u2h(v6), u2h(v7));
        p0 = __hadd2(p0, p1);
        f = __half22float2(p0); bx += f.x; by += f.y;
    }
    for (; e + 2 <= end; e += 2) {
        int s0 = g_col[e], s1 = g_col[e + 1];
        __half2 p = __hadd2(u2h(X[(size_t)s0 * 32 + lane]), u2h(X[(size_t)s1 * 32 + lane]));
        float2 f = __half22float2(p);
        ax += f.x; ay += f.y;
    }
    for (; e < end; e++) {
        int s = g_col[e];
        float2 f = __half22float2(u2h(X[(size_t)s * 32 + lane]));
        ax += f.x; ay += f.y;
    }

    float2 r = ((const float2*)xr)[(size_t)gw * 32 + lane];
    float2 o;
    o.x = (ax + bx) * inv + r.x;
    o.y = (ay + by) * inv + r.y;
    ((float2*)out)[(size_t)gw * 32 + lane] = o;
}

// ============================================================
// Launch — cvt forked onto stream 2, joined before layer-0 agg.
// ============================================================
extern "C" void kernel_launch(void* const* d_in, const int* in_sizes, int n_in,
                              void* d_out, int out_size)
{
    const float* x   = (const float*)d_in[0];
    const int*   ei  = (const int*)d_in[1];
    const float* Wl0 = (const float*)d_in[2];
    const float* Wr0 = (const float*)d_in[3];
    const float* b0  = (const float*)d_in[4];
    const float* Wl1 = (const float*)d_in[5];
    const float* Wr1 = (const float*)d_in[6];
    const float* b1  = (const float*)d_in[7];
    const float* Wl2 = (const float*)d_in[8];
    const float* Wr2 = (const float*)d_in[9];
    const float* b2  = (const float*)d_in[10];

    const int n = in_sizes[0] / 128;
    const int e = in_sizes[1] / 2;
    const int* src = ei;
    const int* dst = ei + e;

    void *px16, *pagg, *pha, *phb, *pxl, *pxr, *pdeg;
    cudaGetSymbolAddress(&px16, g_x16);
    cudaGetSymbolAddress(&pagg, g_agg);
    cudaGetSymbolAddress(&pha, g_ha);
    cudaGetSymbolAddress(&phb, g_hb);
    cudaGetSymbolAddress(&pxl, g_xl);
    cudaGetSymbolAddress(&pxr, g_xr);
    cudaGetSymbolAddress(&pdeg, g_deg);
    __half* f_x16 = (__half*)px16;
    __half* f_agg = (__half*)pagg;
    __half* f_ha  = (__half*)pha;
    __half* f_hb  = (__half*)phb;
    __half* f_xl  = (__half*)pxl;
    float*  f_xr  = (float*)pxr;

    // smem (bytes)
    constexpr int KP = K_DIM + 8;
    constexpr int SM_L01 = (2 * 128 * KP + 2 * 2 * 128 * KP) * 2;  // 208896
    constexpr int SM_H64 = (2 * 64 * KP + 2 * 128 * KP) * 2;       // 104448

    static cudaStream_t s2 = nullptr;
    static cudaEvent_t evFork = nullptr, evJoin = nullptr;
    if (!s2) {
        cudaFuncSetAttribute(gemm_l01, cudaFuncAttributeMaxDynamicSharedMemorySize, SM_L01);
        cudaFuncSetAttribute(gemm_h64, cudaFuncAttributeMaxDynamicSharedMemorySize, SM_H64);
        cudaStreamCreateWithFlags(&s2, cudaStreamNonBlocking);
        cudaEventCreateWithFlags(&evFork, cudaEventDisableTiming);
        cudaEventCreateWithFlags(&evJoin, cudaEventDisableTiming);
    }

    const int NSM = 148;
    const int agg_blocks = (n + 7) / 8;
    const int nb = (n + 1023) / 1024;

    // Fork: x -> fp16 on s2, concurrent with CSR build on stream 0.
    cudaEventRecord(evFork, 0);
    cudaStreamWaitEvent(s2, evFork, 0);
    cvt_x_k<<<(n * 32 + 255) / 256, 256, 0, s2>>>((const float4*)x, (uint2*)f_x16, n * 32);
    cudaEventRecord(evJoin, s2);

    // CSR build (stream 0)
    cudaMemsetAsync(pdeg, 0, (size_t)n * sizeof(int));
    hist_k<<<((e + 3) / 4 + 255) / 256, 256>>>(dst, e);
    scanA_k<<<nb, 1024>>>(n);
    scanC_k<<<nb, 1024>>>(n, nb);
    scatter_k<<<((e + 3) / 4 + 255) / 256, 256>>>(src, dst, e);

    // Join: agg0 needs both CSR and x16.
    cudaStreamWaitEvent(0, evJoin, 0);

    // Layer 0: aggx = mean(x16); h1 = relu(aggx@Wl0 + x16@Wr0 + b0)
    agg_mean128<<<agg_blocks, 256>>>(f_x16, f_agg, n);
    gemm_l01<<<NSM, 512, SM_L01>>>(f_agg, f_x16, Wl0, Wr0, b0, f_ha, n);

    // Layer 1
    agg_mean128<<<agg_blocks, 256>>>(f_ha, f_agg, n);
    gemm_l01<<<NSM, 512, SM_L01>>>(f_agg, f_ha, Wl1, Wr1, b1, f_hb, n);

    // Layer 2 (transform-first, DOUT=64): xl = h2@Wl2, xr = h2@Wr2 + b2
    gemm_h64<<<NSM, 512, SM_H64>>>(f_hb, Wl2, Wr2, b2, f_xl, f_xr, n);
    agg_ep64h<<<agg_blocks, 256>>>(f_xl, f_xr, (float*)d_out, n);
}